// round 6
// baseline (speedup 1.0000x reference)
#include <cuda_runtime.h>
#include <math.h>

#define NB 64
#define HH 30
#define WW 60
#define DD 64
#define NPIX (HH*WW)        // 1800

// ---------------- scratch (device globals; no allocation) ----------------
__device__ float g_cell[NB*8*16*DD];      // hseg-cell sums of x   (2 MB)
__device__ float g_dvec[NB*128*DD];       // d vectors [b][combo][e] (2 MB)
__device__ float g_s[NB*128];
__device__ float g_Mt[DD*DD];             // (Wq^T Wk) transposed: Mt[f][e]
__device__ float g_v1[DD];                // Wq^T bk
__device__ float g_v2[DD];                // Wk^T bq
__device__ float g_cb;                    // bq . bk

// ---------------- geometry LUTs ----------------
__constant__ int c_hstart[8] = {0,6,10,12,15,18,20,24};
__constant__ int c_hlen[8]   = {6,4,2,3,3,2,4,6};
__constant__ int c_wstart[16] = {0,6,10,12,15,18,20,24,30,36,40,42,45,48,50,54};
__constant__ int c_wlen[16]   = {6,4,2,3,3,2,4,6, 6,4,2,3,3,2,4,6};
__constant__ unsigned char c_hseg[30] = {
  0,0,0,0,0,0, 1,1,1,1, 2,2, 3,3,3, 4,4,4, 5,5, 6,6,6,6, 7,7,7,7,7,7};
__constant__ unsigned char c_wseg[60] = {
  0,0,0,0,0,0, 1,1,1,1, 2,2, 3,3,3, 4,4,4, 5,5, 6,6,6,6, 7,7,7,7,7,7,
  8,8,8,8,8,8, 9,9,9,9, 10,10, 11,11,11, 12,12,12, 13,13, 14,14,14,14,
  15,15,15,15,15,15};
// forward maps seg -> pool region index
__constant__ unsigned char c_rh0[8]  = {0,1,1,2,2,3,3,4};
__constant__ unsigned char c_rh1[8]  = {0,0,1,1,1,1,2,2};
__constant__ unsigned char c_rh2[8]  = {0,0,0,0,1,1,1,1};
__constant__ unsigned char c_rw0[16] = {0,1,1,2,2,3,3,4,5,6,6,7,7,8,8,9};
__constant__ unsigned char c_rw1[16] = {0,0,1,1,1,1,2,2,3,3,4,4,4,4,5,5};
__constant__ unsigned char c_rw2[16] = {0,0,0,0,1,1,1,1,2,2,2,2,3,3,3,3};
// inverse maps: region row/col -> [first seg, count] (segments are contiguous)
__constant__ unsigned char p0_hf[5]={0,1,3,5,7},              p0_hc[5]={1,2,2,2,1};
__constant__ unsigned char p0_wf[10]={0,1,3,5,7,8,9,11,13,15},p0_wc[10]={1,2,2,2,1,1,2,2,2,1};
__constant__ unsigned char p1_hf[3]={0,2,6},                  p1_hc[3]={2,4,2};
__constant__ unsigned char p1_wf[6]={0,2,6,8,10,14},          p1_wc[6]={2,4,2,2,4,2};
__constant__ unsigned char p2_hf[2]={0,4},                    p2_hc[2]={4,4};
__constant__ unsigned char p2_wf[4]={0,4,8,12},               p2_wc[4]={4,4,4,4};

// ---------------- kernel A: float4 register-accumulated cell sums + prep ----
// blocks [0,512): (batch, hseg). Thread = (wseg, d-quad): LDG.128 only,
// float4 register accumulation, no smem, no sync, coalesced STG.128.
// blocks [512,528): weight precompute (Mt, v1, v2, cb).
__global__ __launch_bounds__(256) void k_cells(const float* __restrict__ x,
                                               const float* __restrict__ qk_w,
                                               const float* __restrict__ qk_b) {
    int bi = blockIdx.x;
    int tid = threadIdx.x;
    if (bi >= 512) {
        int t = (bi - 512) * 256 + tid;
        int e = t & 63, f = t >> 6;
        float s = 0.f;
        #pragma unroll 8
        for (int d = 0; d < 64; d++)
            s += qk_w[d*64 + e] * qk_w[(64 + d)*64 + f];
        g_Mt[f*64 + e] = s;
        if (bi == 512) {
            if (tid < 64) {
                float a = 0.f;
                for (int d = 0; d < 64; d++) a += qk_w[d*64 + tid] * qk_b[64 + d];
                g_v1[tid] = a;
            } else if (tid < 128) {
                int ff = tid - 64; float a = 0.f;
                for (int d = 0; d < 64; d++) a += qk_w[(64 + d)*64 + ff] * qk_b[d];
                g_v2[ff] = a;
            } else if (tid == 128) {
                float a = 0.f;
                for (int d = 0; d < 64; d++) a += qk_b[d] * qk_b[64 + d];
                g_cb = a;
            }
        }
        return;
    }
    int b = bi >> 3, hs = bi & 7;
    int ws = tid >> 4, j = tid & 15;          // wseg 0..15, d-quad 0..15
    int a0 = c_wstart[ws], l0 = c_wlen[ws];
    int h0 = c_hstart[hs], hl = c_hlen[hs];

    const float4* xb4 = (const float4*)(x + (size_t)(b*HH + h0) * WW * DD);
    float4 acc = make_float4(0.f, 0.f, 0.f, 0.f);
    #pragma unroll 2
    for (int hh = 0; hh < hl; hh++) {
        const float4* xr = xb4 + (hh*WW + a0)*16 + j;
        float4 t = make_float4(0.f, 0.f, 0.f, 0.f);
        #pragma unroll
        for (int w = 0; w < 6; w++) {          // predicated -> up to 6 loads in flight
            if (w < l0) {
                float4 v = xr[w*16];
                t.x += v.x; t.y += v.y; t.z += v.z; t.w += v.w;
            }
        }
        acc.x += t.x; acc.y += t.y; acc.z += t.z; acc.w += t.w;
    }
    float4* dst = (float4*)(g_cell + (size_t)(b*8 + hs) * 1024);
    dst[ws*16 + j] = acc;                      // coalesced STG.128
}

// ---------------- kernel B: fused regions + matvec ----------------
__global__ __launch_bounds__(256) void k_mid(const float* __restrict__ score_w) {
    __shared__ float rs[20*64];                    // 5 KB
    __shared__ __align__(16) float ush[16*64];     // 4 KB
    __shared__ float Msh[4096];                    // 16 KB
    int b = blockIdx.x >> 3, hs = blockIdx.x & 7;
    int tid = threadIdx.x;

    for (int v = tid; v < 4096; v += 256) Msh[v] = g_Mt[v];

    const float* cbp = g_cell + (size_t)b * 8192;
    int rh0 = c_rh0[hs], rh1 = c_rh1[hs], rh2 = c_rh2[hs];
    for (int v = tid; v < 1280; v += 256) {
        int j = v >> 6, d = v & 63;
        int hf, hc, wf, wc;
        if (j < 10)      { hf=p0_hf[rh0]; hc=p0_hc[rh0]; wf=p0_wf[j];    wc=p0_wc[j]; }
        else if (j < 16) { int rw=j-10; hf=p1_hf[rh1]; hc=p1_hc[rh1]; wf=p1_wf[rw]; wc=p1_wc[rw]; }
        else             { int rw=j-16; hf=p2_hf[rh2]; hc=p2_hc[rh2]; wf=p2_wf[rw]; wc=p2_wc[rw]; }
        float s = 0.f;
        for (int a = 0; a < hc; a++)
            for (int c2 = 0; c2 < wc; c2++)
                s += cbp[(hf + a)*1024 + (wf + c2)*64 + d];
        rs[v] = s;
    }
    __syncthreads();

    float w0 = score_w[0], w1 = score_w[1], w2 = score_w[2];
    float a0 = w0*(1.f/36.f), a1 = w1*(1.f/100.f), a2 = w2*(1.f/225.f);
    float wsum = w0 + w1 + w2;

    for (int v = tid; v < 1024; v += 256) {
        int ws = v >> 6, f = v & 63;
        ush[v] = a0*rs[(int)c_rw0[ws]*64 + f]
               + a1*rs[(10 + (int)c_rw1[ws])*64 + f]
               + a2*rs[(16 + (int)c_rw2[ws])*64 + f];
    }
    __syncthreads();

    // s[c] = v2 . u[c] + wsum*cb
    int lane = tid & 31, warp = tid >> 5;
    for (int ws = warp; ws < 16; ws += 8) {
        float sv = ush[ws*64 + lane]      * g_v2[lane]
                 + ush[ws*64 + 32 + lane] * g_v2[32 + lane];
        #pragma unroll
        for (int o = 16; o; o >>= 1) sv += __shfl_xor_sync(0xffffffffu, sv, o);
        if (lane == 0) g_s[b*128 + hs*16 + ws] = sv + wsum * g_cb;
    }

    // matvec
    int e = tid & 63, cg = tid >> 6;
    float init = wsum * g_v1[e];
    float acc0 = init, acc1 = init, acc2 = init, acc3 = init;
    const float4* u0 = (const float4*)(ush + (cg*4 + 0)*64);
    const float4* u1 = (const float4*)(ush + (cg*4 + 1)*64);
    const float4* u2 = (const float4*)(ush + (cg*4 + 2)*64);
    const float4* u3 = (const float4*)(ush + (cg*4 + 3)*64);
    #pragma unroll
    for (int fq = 0; fq < 16; fq++) {
        int f = fq*4;
        float m0 = Msh[(f+0)*64 + e];
        float m1 = Msh[(f+1)*64 + e];
        float m2 = Msh[(f+2)*64 + e];
        float m3 = Msh[(f+3)*64 + e];
        float4 a = u0[fq], bb = u1[fq], c = u2[fq], dd = u3[fq];
        acc0 += m0*a.x  + m1*a.y  + m2*a.z  + m3*a.w;
        acc1 += m0*bb.x + m1*bb.y + m2*bb.z + m3*bb.w;
        acc2 += m0*c.x  + m1*c.y  + m2*c.z  + m3*c.w;
        acc3 += m0*dd.x + m1*dd.y + m2*dd.z + m3*dd.w;
    }
    float* dst = g_dvec + ((size_t)(b*128 + hs*16 + cg*4))*64;
    dst[0*64 + e] = acc0;
    dst[1*64 + e] = acc1;
    dst[2*64 + e] = acc2;
    dst[3*64 + e] = acc3;
}

// ---------------- kernel C: per-pixel dot + gumbel-softmax ----------------
__global__ __launch_bounds__(256) void k_final(const float* __restrict__ x,
                                               const float* __restrict__ score_b,
                                               const float* __restrict__ noise_x,
                                               const float* __restrict__ noise_r,
                                               float* __restrict__ out) {
    __shared__ __align__(16) float dsh[1024];
    __shared__ float bsh[16];                 // 0.125*s + score_b
    __shared__ float ash[64];
    int bh = blockIdx.x;
    int b = bh / HH, h = bh - b*HH;
    int hs = c_hseg[h];
    int tid = threadIdx.x;

    // hoist noise loads: DRAM latency overlaps the whole dot phase
    int gi = bh * WW + tid;
    float nxv = 0.f, nrv = 0.f;
    if (tid < WW) { nxv = noise_x[gi]; nrv = noise_r[gi]; }

    const float* dsrc = g_dvec + ((size_t)(b*128 + hs*16))*64;
    for (int v = tid; v < 1024; v += 256) dsh[v] = dsrc[v];
    if (tid < 16) bsh[tid] = 0.125f * g_s[b*128 + hs*16 + tid] + score_b[0];
    __syncthreads();

    int lane = tid & 31, warp = tid >> 5;
    int half = lane >> 4, j = lane & 15;
    const float4* xr4 = (const float4*)(x + (size_t)bh * WW * DD);

    int p0 = warp*2 + half;                   // 0..15
    int p3 = p0 + 48;
    bool v3 = (p3 < WW);
    float4 a0 = xr4[(p0      )*16 + j];
    float4 a1 = xr4[(p0 + 16)*16 + j];
    float4 a2 = xr4[(p0 + 32)*16 + j];
    float4 a3 = v3 ? xr4[p3*16 + j] : make_float4(0.f,0.f,0.f,0.f);

    int ws0 = c_wseg[p0], ws1 = c_wseg[p0+16], ws2 = c_wseg[p0+32];
    int ws3 = v3 ? (int)c_wseg[p3] : 0;
    float4 d0 = ((const float4*)(dsh + ws0*64))[j];
    float4 d1 = ((const float4*)(dsh + ws1*64))[j];
    float4 d2 = ((const float4*)(dsh + ws2*64))[j];
    float4 d3 = ((const float4*)(dsh + ws3*64))[j];

    float t0 = a0.x*d0.x + a0.y*d0.y + a0.z*d0.z + a0.w*d0.w;
    float t1 = a1.x*d1.x + a1.y*d1.y + a1.z*d1.z + a1.w*d1.w;
    float t2 = a2.x*d2.x + a2.y*d2.y + a2.z*d2.z + a2.w*d2.w;
    float t3 = a3.x*d3.x + a3.y*d3.y + a3.z*d3.z + a3.w*d3.w;

    #pragma unroll
    for (int o = 1; o < 16; o <<= 1) {
        t0 += __shfl_xor_sync(0xffffffffu, t0, o);
        t1 += __shfl_xor_sync(0xffffffffu, t1, o);
        t2 += __shfl_xor_sync(0xffffffffu, t2, o);
        t3 += __shfl_xor_sync(0xffffffffu, t3, o);
    }
    if (j == 0) {
        ash[p0]      = 0.125f*t0 + bsh[ws0];
        ash[p0 + 16] = 0.125f*t1 + bsh[ws1];
        ash[p0 + 32] = 0.125f*t2 + bsh[ws2];
        if (v3) ash[p3] = 0.125f*t3 + bsh[ws3];
    }
    __syncthreads();

    if (tid < WW) {
        float attn = ash[tid];
        float sig  = 1.f / (1.f + expf(-attn));
        float gx   = logf(sig + 1e-8f);
        float gr   = logf(1.f - sig + 1e-8f);
        float nx   = -logf(-logf(nxv + 1e-8f) + 1e-8f);
        float nr   = -logf(-logf(nrv + 1e-8f) + 1e-8f);
        const float invT = 1.f / (0.03f + 1e-8f);
        float l = (gx + nx)*invT - (gr + nr)*invT;
        out[gi] = 1.f / (1.f + expf(-l));
    }
}

// ---------------- launcher ----------------
extern "C" void kernel_launch(void* const* d_in, const int* in_sizes, int n_in,
                              void* d_out, int out_size) {
    const float* x       = (const float*)d_in[0];   // (64,30,60,64)
    const float* qk_w    = (const float*)d_in[1];   // (128,64)
    const float* qk_b    = (const float*)d_in[2];   // (128,)
    const float* score_w = (const float*)d_in[3];   // (1,3)
    const float* score_b = (const float*)d_in[4];   // (1,)
    const float* noise_x = (const float*)d_in[5];   // (64,1800,1)
    const float* noise_r = (const float*)d_in[6];   // (64,1800,1)
    float* out = (float*)d_out;                     // (64,1800,1)

    k_cells<<<528,   256>>>(x, qk_w, qk_b);
    k_mid  <<<NB*8,  256>>>(score_w);
    k_final<<<NB*HH, 256>>>(x, score_b, noise_x, noise_r, out);
}